// round 14
// baseline (speedup 1.0000x reference)
#include <cuda_runtime.h>
#include <float.h>

#define NATOMS 10000
#define NPAIRS 160000
#define HPITCH 192   // padded h row: [q0(128) | filtered(50) | d(1) | zero pad(13)]
#define SAP 260      // padded sA stride (words)

// ---------------- scratch (device globals; no allocation allowed) ----------------
__device__ float g_h[(size_t)NPAIRS * HPITCH];     // edge feature rows
__device__ float g_hidden[(size_t)NPAIRS * 64];
__device__ float g_m[(size_t)NPAIRS * 64];         // q_ij_mtx
__device__ float g_att[(size_t)NPAIRS * 4];
__device__ float g_e[(size_t)NPAIRS * 4];
__device__ float g_comb[(size_t)NPAIRS * 4];       // e / denom[idx_j]
__device__ float g_segmax[NATOMS * 4];
__device__ float g_denom[NATOMS * 4];
__device__ int   g_counts[NATOMS];
__device__ int   g_cursor[NATOMS];
__device__ int   g_offs[NATOMS + 1];
__device__ int   g_order[NPAIRS];
__device__ float g_coeffs[(size_t)NPAIRS * 256];
__device__ float g_norm[(size_t)NATOMS * 256];
__device__ float g_h2[(size_t)NATOMS * 384];       // [q(64) | q_ij(256) | q_comb(64)]
__device__ float g_t1[(size_t)NATOMS * 64];
__device__ float g_t2[(size_t)NATOMS * 64];

// ---------------- helpers ----------------
__device__ __forceinline__ float siluf(float x) { return x / (1.f + __expf(-x)); }
__device__ __forceinline__ float fast_tanh(float x) {
    return 1.f - 2.f / (__expf(2.f * x) + 1.f);
}
__device__ __forceinline__ void atomicMaxFloat(float* a, float v) {
    if (v >= 0.f) atomicMax((int*)a, __float_as_int(v));
    else          atomicMin((unsigned int*)a, __float_as_uint(v));
}
__device__ __forceinline__ unsigned f2tf32(float x) {
    unsigned r;
    asm("cvt.rna.tf32.f32 %0, %1;" : "=r"(r) : "f"(x));
    return r;
}
__device__ __forceinline__ void mma_tf32(float* d, const unsigned* a, const unsigned* b) {
    asm volatile(
        "mma.sync.aligned.m16n8k8.row.col.f32.tf32.tf32.f32 "
        "{%0,%1,%2,%3}, {%4,%5,%6,%7}, {%8,%9}, {%0,%1,%2,%3};"
        : "+f"(d[0]), "+f"(d[1]), "+f"(d[2]), "+f"(d[3])
        : "r"(a[0]), "r"(a[1]), "r"(a[2]), "r"(a[3]), "r"(b[0]), "r"(b[1]));
}

// ---------------- init ----------------
__global__ void k_init() {
    int i = blockIdx.x * blockDim.x + threadIdx.x;
    if (i < NATOMS * 4) { g_segmax[i] = -FLT_MAX; g_denom[i] = 0.f; }
    if (i < NATOMS)     { g_counts[i] = 0; g_cursor[i] = 0; }
}

// ---------------- gather: build q0 | d | zero-pad rows of g_h ----------------
__global__ void k_gather(const float* __restrict__ q, const int* __restrict__ idx_i,
                         const int* __restrict__ idx_j, const float* __restrict__ d_ij) {
    int p    = blockIdx.x * 8 + (threadIdx.x >> 5);
    int lane = threadIdx.x & 31;
    int i = idx_i[p], j = idx_j[p];
    float* hr = g_h + (size_t)p * HPITCH;
    const float* qi = q + (size_t)i * 64;
    const float* qj = q + (size_t)j * 64;
    hr[lane]      = qi[lane];       hr[32 + lane] = qi[32 + lane];
    hr[64 + lane] = qj[lane];       hr[96 + lane] = qj[32 + lane];
    if (lane < 14) hr[178 + lane] = (lane == 0) ? d_ij[p] : 0.f;
}

// ================= pair-level GEMM (FFMA), fat tiles, coalesced staging ========
// MODE 0: h[:, :128] @ w_in^T,  epi: rbf * (.)  -> writes g_h cols 128..177
// MODE 1: h @ w_out1^T, silu -> g_hidden
// MODE 2: hidden @ w_out2^T, +bias -> g_m
template <int MODE>
__global__ void __launch_bounds__(256, 2)
k_gemm2(const float* __restrict__ W, const float* __restrict__ bias,
        const float* __restrict__ d_ij, const float* __restrict__ roffs,
        const float* __restrict__ rwids) {
    constexpr int KT  = (MODE == 0) ? 8 : (MODE == 1) ? 12 : 4;
    constexpr int KW  = (MODE == 0) ? 128 : (MODE == 1) ? 179 : 64;
    constexpr int NW  = (MODE == 0) ? 50 : 64;
    constexpr int LDA = (MODE <= 1) ? HPITCH : 64;
    constexpr int LDC = (MODE == 0) ? HPITCH : 64;

    const float* A = (MODE == 2) ? g_hidden : g_h;
    float* C = (MODE == 0) ? (g_h + 128) : (MODE == 1) ? g_hidden : g_m;

    __shared__ __align__(16) float sA[16 * SAP];
    __shared__ __align__(16) float sW[16 * 68];

    const int t  = threadIdx.x;
    const int p0 = blockIdx.x * 256;
    const int tx = t & 7;
    const int ty = t >> 3;
    const int mrl = t >> 2;
    const int ak  = (t & 3) * 4;
    const int wr = t >> 2;
    const int wk = (t & 3) * 4;
    const size_t wbase = (size_t)wr * KW;

    float acc[8][8];
#pragma unroll
    for (int i = 0; i < 8; i++)
#pragma unroll
        for (int j = 0; j < 8; j++) acc[i][j] = 0.f;

    float4 pa[4];
    float  pw[4];

    {
#pragma unroll
        for (int r = 0; r < 4; r++)
            pa[r] = *reinterpret_cast<const float4*>(
                A + (size_t)(p0 + r * 64 + mrl) * LDA + ak);
#pragma unroll
        for (int j = 0; j < 4; j++) {
            int k = wk + j;
            bool ok = true;
            if constexpr (NW < 64) ok = (wr < NW);
            if constexpr ((KW & 15) != 0) ok = ok && (k < KW);
            pw[j] = ok ? __ldg(&W[wbase + k]) : 0.f;
        }
    }

    for (int kt = 0; kt < KT; kt++) {
        __syncthreads();
#pragma unroll
        for (int r = 0; r < 4; r++) {
            int mi = r * 64 + mrl;
            sA[(ak + 0) * SAP + mi] = pa[r].x;
            sA[(ak + 1) * SAP + mi] = pa[r].y;
            sA[(ak + 2) * SAP + mi] = pa[r].z;
            sA[(ak + 3) * SAP + mi] = pa[r].w;
        }
#pragma unroll
        for (int j = 0; j < 4; j++) sW[(wk + j) * 68 + wr] = pw[j];
        __syncthreads();

        if (kt + 1 < KT) {
            int k0 = (kt + 1) * 16;
#pragma unroll
            for (int r = 0; r < 4; r++)
                pa[r] = *reinterpret_cast<const float4*>(
                    A + (size_t)(p0 + r * 64 + mrl) * LDA + k0 + ak);
#pragma unroll
            for (int j = 0; j < 4; j++) {
                int k = k0 + wk + j;
                bool ok = true;
                if constexpr (NW < 64) ok = (wr < NW);
                if constexpr ((KW & 15) != 0) ok = ok && (k < KW);
                pw[j] = ok ? __ldg(&W[wbase + k]) : 0.f;
            }
        }

#pragma unroll
        for (int kk = 0; kk < 16; kk++) {
            float4 a0 = *reinterpret_cast<const float4*>(&sA[kk * SAP + ty * 8]);
            float4 a1 = *reinterpret_cast<const float4*>(&sA[kk * SAP + ty * 8 + 4]);
            float4 b0 = *reinterpret_cast<const float4*>(&sW[kk * 68 + tx * 8]);
            float4 b1 = *reinterpret_cast<const float4*>(&sW[kk * 68 + tx * 8 + 4]);
            float av[8] = {a0.x, a0.y, a0.z, a0.w, a1.x, a1.y, a1.z, a1.w};
            float bv[8] = {b0.x, b0.y, b0.z, b0.w, b1.x, b1.y, b1.z, b1.w};
#pragma unroll
            for (int i = 0; i < 8; i++)
#pragma unroll
                for (int j = 0; j < 8; j++)
                    acc[i][j] += av[i] * bv[j];
        }
    }

    if constexpr (MODE == 0) {
#pragma unroll
        for (int i = 0; i < 8; i++) {
            int p = p0 + ty * 8 + i;
            float dv = __ldg(&d_ij[p]);
#pragma unroll
            for (int j = 0; j < 8; j++) {
                int gn = tx * 8 + j;
                if (gn < 50) {
                    float off = __ldg(&roffs[gn]), wd = __ldg(&rwids[gn]);
                    float dd = dv - off;
                    float r = __expf((-0.5f / (wd * wd)) * dd * dd);
                    C[(size_t)p * LDC + gn] = r * (acc[i][j] + __ldg(&bias[gn]));
                }
            }
        }
    } else {
        float bb[8];
#pragma unroll
        for (int j = 0; j < 8; j++) bb[j] = __ldg(&bias[tx * 8 + j]);
#pragma unroll
        for (int i = 0; i < 8; i++) {
            int p = p0 + ty * 8 + i;
            float4 v0, v1;
            if constexpr (MODE == 2) {
                v0.x = acc[i][0] + bb[0]; v0.y = acc[i][1] + bb[1];
                v0.z = acc[i][2] + bb[2]; v0.w = acc[i][3] + bb[3];
                v1.x = acc[i][4] + bb[4]; v1.y = acc[i][5] + bb[5];
                v1.z = acc[i][6] + bb[6]; v1.w = acc[i][7] + bb[7];
            } else {
                v0.x = siluf(acc[i][0] + bb[0]); v0.y = siluf(acc[i][1] + bb[1]);
                v0.z = siluf(acc[i][2] + bb[2]); v0.w = siluf(acc[i][3] + bb[3]);
                v1.x = siluf(acc[i][4] + bb[4]); v1.y = siluf(acc[i][5] + bb[5]);
                v1.z = siluf(acc[i][6] + bb[6]); v1.w = siluf(acc[i][7] + bb[7]);
            }
            float* cp = C + (size_t)p * 64 + tx * 8;
            *reinterpret_cast<float4*>(cp)     = v0;
            *reinterpret_cast<float4*>(cp + 4) = v1;
        }
    }
}

// ================= mixing GEMM on tensor cores (tf32 mma.sync) =================
// C[p, n] = tanh( sum_k A[p,k] * w_mix[n,k] ),  A[p,k] = m[p,k>>2]*comb[p,k&3]
// grid (1250, 2): block tile 128 M x 128 N; 8 warps in 4x2; warp tile 32x64.
// K = 256 in 8 chunks of BK=32. Single-buffer smem + register prefetch.
#define MMP 36   // smem row pitch (words): 4*gid+tig covers 0..31 -> conflict-free
__global__ void __launch_bounds__(256, 2)
k_mix_mma(const float* __restrict__ W) {
    __shared__ unsigned sA[128 * MMP];   // [m][k] tf32 bits
    __shared__ unsigned sB[128 * MMP];   // [n][k] tf32 bits

    const int t    = threadIdx.x;
    const int lane = t & 31;
    const int warp = t >> 5;
    const int gid  = lane >> 2;
    const int tig  = lane & 3;
    const int warpM = warp & 3;        // 0..3  -> 32 rows each
    const int warpN = warp >> 2;       // 0..1  -> 64 cols each
    const int p0 = blockIdx.x * 128;
    const int n0 = blockIdx.y * 128;

    // staging assignment: 2 threads per row
    const int srow = t >> 1;           // 0..127
    const int shalf = t & 1;           // k-half of 16

    const float4 cb = *reinterpret_cast<const float4*>(&g_comb[(size_t)(p0 + srow) * 4]);
    const float cbv[4] = {cb.x, cb.y, cb.z, cb.w};

    float d[2][8][4];
#pragma unroll
    for (int mt = 0; mt < 2; mt++)
#pragma unroll
        for (int nf = 0; nf < 8; nf++)
#pragma unroll
            for (int v = 0; v < 4; v++) d[mt][nf][v] = 0.f;

    float4 pmv;        // prefetched m (4 values)
    float4 pwv[4];     // prefetched W (16 values)

    // prefetch chunk 0
    pmv = *reinterpret_cast<const float4*>(&g_m[(size_t)(p0 + srow) * 64 + shalf * 4]);
#pragma unroll
    for (int i = 0; i < 4; i++)
        pwv[i] = *reinterpret_cast<const float4*>(
            &W[(size_t)(n0 + srow) * 256 + shalf * 16 + i * 4]);

    for (int kc = 0; kc < 8; kc++) {
        __syncthreads();
        // ---- store staged chunk ----
        {
            const float mv[4] = {pmv.x, pmv.y, pmv.z, pmv.w};
            unsigned* ap = &sA[srow * MMP + shalf * 16];
#pragma unroll
            for (int i = 0; i < 4; i++)
#pragma unroll
                for (int j = 0; j < 4; j++)
                    ap[i * 4 + j] = f2tf32(mv[i] * cbv[j]);
            unsigned* bp = &sB[srow * MMP + shalf * 16];
            const float wv[16] = {pwv[0].x, pwv[0].y, pwv[0].z, pwv[0].w,
                                  pwv[1].x, pwv[1].y, pwv[1].z, pwv[1].w,
                                  pwv[2].x, pwv[2].y, pwv[2].z, pwv[2].w,
                                  pwv[3].x, pwv[3].y, pwv[3].z, pwv[3].w};
#pragma unroll
            for (int i = 0; i < 16; i++) bp[i] = f2tf32(wv[i]);
        }
        __syncthreads();

        // ---- prefetch next chunk ----
        if (kc + 1 < 8) {
            int k0 = (kc + 1) * 32;
            pmv = *reinterpret_cast<const float4*>(
                &g_m[(size_t)(p0 + srow) * 64 + (k0 >> 2) + shalf * 4]);
#pragma unroll
            for (int i = 0; i < 4; i++)
                pwv[i] = *reinterpret_cast<const float4*>(
                    &W[(size_t)(n0 + srow) * 256 + k0 + shalf * 16 + i * 4]);
        }

        // ---- compute: 4 k-steps of 8, 16 mma each ----
#pragma unroll
        for (int ks = 0; ks < 4; ks++) {
            const int kb = ks * 8;
            unsigned a[2][4];
#pragma unroll
            for (int mt = 0; mt < 2; mt++) {
                const int mb = warpM * 32 + mt * 16;
                a[mt][0] = sA[(mb + gid) * MMP + kb + tig];
                a[mt][1] = sA[(mb + gid + 8) * MMP + kb + tig];
                a[mt][2] = sA[(mb + gid) * MMP + kb + tig + 4];
                a[mt][3] = sA[(mb + gid + 8) * MMP + kb + tig + 4];
            }
#pragma unroll
            for (int nf = 0; nf < 8; nf++) {
                unsigned b[2];
                const int nb = warpN * 64 + nf * 8 + gid;
                b[0] = sB[nb * MMP + kb + tig];
                b[1] = sB[nb * MMP + kb + tig + 4];
                mma_tf32(d[0][nf], a[0], b);
                mma_tf32(d[1][nf], a[1], b);
            }
        }
    }

    // ---- epilogue: tanh, write g_coeffs ----
#pragma unroll
    for (int mt = 0; mt < 2; mt++) {
        const int prow = p0 + warpM * 32 + mt * 16 + gid;
#pragma unroll
        for (int nf = 0; nf < 8; nf++) {
            const int col = n0 + warpN * 64 + nf * 8 + tig * 2;
            float2 lo, hi;
            lo.x = fast_tanh(d[mt][nf][0]); lo.y = fast_tanh(d[mt][nf][1]);
            hi.x = fast_tanh(d[mt][nf][2]); hi.y = fast_tanh(d[mt][nf][3]);
            *reinterpret_cast<float2*>(&g_coeffs[(size_t)prow * 256 + col]) = lo;
            *reinterpret_cast<float2*>(&g_coeffs[(size_t)(prow + 8) * 256 + col]) = hi;
        }
    }
}

// ================= atom-level GEMM (small M): 64x64 tiles =================
// MODE 4: norm @ w_post1^T, silu -> g_t1
// MODE 5: t1 @ w_post2^T, silu -> g_h2[:, 320:384]
// MODE 6: h2 @ w_node1^T, silu -> g_t2
// MODE 7: t2 @ w_node2^T, q + silu(.) -> out
template <int MODE>
__global__ void k_gemm(const float* __restrict__ W, const float* __restrict__ bias,
                       const float* __restrict__ x1, float* __restrict__ outp) {
    constexpr int M  = NATOMS;
    constexpr int KT = (MODE == 4) ? 16 : (MODE == 5) ? 4 : (MODE == 6) ? 24 : 4;
    constexpr int KW = (MODE == 4) ? 256 : (MODE == 5) ? 64 : (MODE == 6) ? 384 : 64;
    constexpr int LDA = (MODE == 4) ? 256 : (MODE == 6) ? 384 : 64;
    constexpr int LDC = (MODE == 5) ? 384 : 64;

    const float* A;
    float* C;
    if constexpr (MODE == 4)      { A = g_norm;   C = g_t1;      }
    else if constexpr (MODE == 5) { A = g_t1;     C = g_h2 + 320;}
    else if constexpr (MODE == 6) { A = g_h2;     C = g_t2;      }
    else                          { A = g_t2;     C = outp;      }

    __shared__ __align__(16) float sA[16 * 68];
    __shared__ __align__(16) float sW[16 * 68];

    int t  = threadIdx.x;
    int p0 = blockIdx.x * 64;
    int tx = t & 15, ty = t >> 4;
    int am   = t >> 2;
    int ak   = (t & 3) * 4;
    int arow = p0 + am;

    float acc[4][4];
#pragma unroll
    for (int i = 0; i < 4; i++)
#pragma unroll
        for (int j = 0; j < 4; j++) acc[i][j] = 0.f;

    for (int kt = 0; kt < KT; kt++) {
        int k0 = kt * 16;
        float4 av = make_float4(0.f, 0.f, 0.f, 0.f);
        if (arow < M)
            av = *reinterpret_cast<const float4*>(A + (size_t)arow * LDA + k0 + ak);
        float wv[4];
#pragma unroll
        for (int j = 0; j < 4; j++) {
            int k = k0 + ak + j;
            wv[j] = (k < KW) ? __ldg(&W[(size_t)am * KW + k]) : 0.f;
        }
        __syncthreads();
        sA[(ak + 0) * 68 + am] = av.x; sA[(ak + 1) * 68 + am] = av.y;
        sA[(ak + 2) * 68 + am] = av.z; sA[(ak + 3) * 68 + am] = av.w;
#pragma unroll
        for (int j = 0; j < 4; j++) sW[(ak + j) * 68 + am] = wv[j];
        __syncthreads();
#pragma unroll
        for (int kk = 0; kk < 16; kk++) {
            float4 a = *reinterpret_cast<const float4*>(&sA[kk * 68 + ty * 4]);
            float4 b = *reinterpret_cast<const float4*>(&sW[kk * 68 + tx * 4]);
            acc[0][0] += a.x * b.x; acc[0][1] += a.x * b.y; acc[0][2] += a.x * b.z; acc[0][3] += a.x * b.w;
            acc[1][0] += a.y * b.x; acc[1][1] += a.y * b.y; acc[1][2] += a.y * b.z; acc[1][3] += a.y * b.w;
            acc[2][0] += a.z * b.x; acc[2][1] += a.z * b.y; acc[2][2] += a.z * b.z; acc[2][3] += a.z * b.w;
            acc[3][0] += a.w * b.x; acc[3][1] += a.w * b.y; acc[3][2] += a.w * b.z; acc[3][3] += a.w * b.w;
        }
    }

#pragma unroll
    for (int i = 0; i < 4; i++) {
        int p = p0 + ty * 4 + i;
        if (p >= M) continue;
#pragma unroll
        for (int j = 0; j < 4; j++) {
            int gn = tx * 4 + j;
            float v = acc[i][j];
            if constexpr (MODE == 7) {
                C[(size_t)p * LDC + gn] = x1[(size_t)p * 64 + gn] + siluf(v + bias[gn]);
            } else {
                C[(size_t)p * LDC + gn] = siluf(v + bias[gn]);
            }
        }
    }
}

// ---------------- attention logits + segment max + degree counts ----------------
__global__ void k_att(const float* __restrict__ w_att, const float* __restrict__ b_att,
                      const int* __restrict__ idx_j) {
    int p    = blockIdx.x * 8 + (threadIdx.x >> 5);
    int lane = threadIdx.x & 31;
    const float* mr = g_m + (size_t)p * 64;
    float m1 = mr[lane], m2 = mr[32 + lane];
    float pa[4];
#pragma unroll
    for (int a = 0; a < 4; a++)
        pa[a] = __ldg(&w_att[a * 64 + lane]) * m1 + __ldg(&w_att[a * 64 + 32 + lane]) * m2;
#pragma unroll
    for (int o = 16; o > 0; o >>= 1)
#pragma unroll
        for (int a = 0; a < 4; a++) pa[a] += __shfl_xor_sync(0xffffffffu, pa[a], o);
    if (lane == 0) {
        int j = idx_j[p];
#pragma unroll
        for (int a = 0; a < 4; a++) {
            float v = pa[a] + b_att[a];
            v = (v >= 0.f) ? v : 2.f * expm1f(0.5f * v);   // celu alpha=2
            g_att[p * 4 + a] = v;
            atomicMaxFloat(&g_segmax[j * 4 + a], v);
        }
        atomicAdd(&g_counts[j], 1);
    }
}

// ---------------- softmax numerators + denominators ----------------
__global__ void k_exp(const int* __restrict__ idx_j) {
    int p = blockIdx.x * blockDim.x + threadIdx.x;
    if (p >= NPAIRS) return;
    int j = idx_j[p];
#pragma unroll
    for (int a = 0; a < 4; a++) {
        float v = __expf(g_att[p * 4 + a] - g_segmax[j * 4 + a]);
        g_e[p * 4 + a] = v;
        atomicAdd(&g_denom[j * 4 + a], v);
    }
}

// ---------------- comb = e / denom[idx_j] ----------------
__global__ void k_comb(const int* __restrict__ idx_j) {
    int p = blockIdx.x * blockDim.x + threadIdx.x;
    if (p >= NPAIRS) return;
    int j = idx_j[p];
    float4 e4 = *reinterpret_cast<const float4*>(&g_e[(size_t)p * 4]);
    float4 d4 = *reinterpret_cast<const float4*>(&g_denom[(size_t)j * 4]);
    float4 c4 = make_float4(e4.x / d4.x, e4.y / d4.y, e4.z / d4.z, e4.w / d4.w);
    *reinterpret_cast<float4*>(&g_comb[(size_t)p * 4]) = c4;
}

// ---------------- exclusive scan of counts -> offs (single block) ----------------
__global__ void k_scan() {
    __shared__ int part[1024];
    int tid = threadIdx.x;
    int base = tid * 10;
    int loc[10];
    int s = 0;
#pragma unroll
    for (int j = 0; j < 10; j++) {
        int idx = base + j;
        int v = (idx < NATOMS) ? g_counts[idx] : 0;
        loc[j] = s; s += v;
    }
    part[tid] = s;
    __syncthreads();
    for (int off = 1; off < 1024; off <<= 1) {
        int v = (tid >= off) ? part[tid - off] : 0;
        __syncthreads();
        part[tid] += v;
        __syncthreads();
    }
    int pre = (tid > 0) ? part[tid - 1] : 0;
#pragma unroll
    for (int j = 0; j < 10; j++) {
        int idx = base + j;
        if (idx < NATOMS) g_offs[idx] = pre + loc[j];
    }
    if (tid == 1023) g_offs[NATOMS] = part[1023];
}

// ---------------- fill CSR edge order ----------------
__global__ void k_fill(const int* __restrict__ idx_j) {
    int p = blockIdx.x * blockDim.x + threadIdx.x;
    if (p >= NPAIRS) return;
    int j = idx_j[p];
    int pos = atomicAdd(&g_cursor[j], 1);
    g_order[g_offs[j] + pos] = p;
}

// ---------------- per-atom gather reductions: q_ij, norm; also copy q into h2 ----
__global__ void k_segreduce(const float* __restrict__ q, const float* __restrict__ r_ij,
                            const float* __restrict__ d_ij) {
    int n    = blockIdx.x * 8 + (threadIdx.x >> 5);
    int lane = threadIdx.x & 31;
    if (n >= NATOMS) return;
    int beg = g_offs[n], end = g_offs[n + 1];
    int cnt = end - beg;
    float inv = 1.f / (float)max(cnt, 1);
    g_h2[(size_t)n * 384 + lane]      = q[(size_t)n * 64 + lane];
    g_h2[(size_t)n * 384 + 32 + lane] = q[(size_t)n * 64 + 32 + lane];
    for (int cr = 0; cr < 8; cr++) {
        int c = cr * 32 + lane;
        int f = c >> 2, hh = c & 3;
        float ax = 0.f, ay = 0.f, az = 0.f, aq = 0.f;
        for (int tt = beg; tt < end; tt++) {
            int p = g_order[tt];
            float co   = __ldg(&g_coeffs[(size_t)p * 256 + c]);
            float rinv = 1.f / (__ldg(&d_ij[p]) + 1e-5f);
            ax += co * __ldg(&r_ij[p * 3 + 0]) * rinv;
            ay += co * __ldg(&r_ij[p * 3 + 1]) * rinv;
            az += co * __ldg(&r_ij[p * 3 + 2]) * rinv;
            aq += __ldg(&g_m[(size_t)p * 64 + f]) * __ldg(&g_comb[p * 4 + hh]);
        }
        float mx = ax * inv, my = ay * inv, mz = az * inv;
        g_norm[(size_t)n * 256 + c]     = mx * mx + my * my + mz * mz;
        g_h2[(size_t)n * 384 + 64 + c]  = aq;
    }
}

// ---------------- launch ----------------
extern "C" void kernel_launch(void* const* d_in, const int* in_sizes, int n_in,
                              void* d_out, int out_size) {
    (void)in_sizes; (void)n_in; (void)out_size;
    const float* q       = (const float*)d_in[0];
    const float* r_ij    = (const float*)d_in[2];
    const float* d_ij    = (const float*)d_in[3];
    const int*   idx_i   = (const int*)d_in[4];
    const int*   idx_j   = (const int*)d_in[5];
    const float* rbf_off = (const float*)d_in[6];
    const float* rbf_w   = (const float*)d_in[7];
    const float* w_in    = (const float*)d_in[8];
    const float* b_in    = (const float*)d_in[9];
    const float* w_out1  = (const float*)d_in[10];
    const float* b_out1  = (const float*)d_in[11];
    const float* w_out2  = (const float*)d_in[12];
    const float* b_out2  = (const float*)d_in[13];
    const float* w_att   = (const float*)d_in[14];
    const float* b_att   = (const float*)d_in[15];
    const float* w_mix   = (const float*)d_in[16];
    const float* w_post1 = (const float*)d_in[17];
    const float* b_post1 = (const float*)d_in[18];
    const float* w_post2 = (const float*)d_in[19];
    const float* b_post2 = (const float*)d_in[20];
    const float* w_node1 = (const float*)d_in[21];
    const float* b_node1 = (const float*)d_in[22];
    const float* w_node2 = (const float*)d_in[23];
    const float* b_node2 = (const float*)d_in[24];
    float* out = (float*)d_out;

    k_init<<<157, 256>>>();
    k_gather<<<NPAIRS / 8, 256>>>(q, idx_i, idx_j, d_ij);
    k_gemm2<0><<<NPAIRS / 256, 256>>>(w_in, b_in, d_ij, rbf_off, rbf_w);
    k_gemm2<1><<<NPAIRS / 256, 256>>>(w_out1, b_out1, nullptr, nullptr, nullptr);
    k_gemm2<2><<<NPAIRS / 256, 256>>>(w_out2, b_out2, nullptr, nullptr, nullptr);
    k_att<<<NPAIRS / 8, 256>>>(w_att, b_att, idx_j);
    k_exp<<<(NPAIRS + 255) / 256, 256>>>(idx_j);
    k_comb<<<(NPAIRS + 255) / 256, 256>>>(idx_j);
    k_scan<<<1, 1024>>>();
    k_fill<<<(NPAIRS + 255) / 256, 256>>>(idx_j);
    k_mix_mma<<<dim3(NPAIRS / 128, 2), 256>>>(w_mix);
    k_segreduce<<<NATOMS / 8, 256>>>(q, r_ij, d_ij);
    k_gemm<4><<<157, 256>>>(w_post1, b_post1, nullptr, nullptr);
    k_gemm<5><<<157, 256>>>(w_post2, b_post2, nullptr, nullptr);
    k_gemm<6><<<157, 256>>>(w_node1, b_node1, nullptr, nullptr);
    k_gemm<7><<<157, 256>>>(w_node2, b_node2, q, out);
}

// round 16
// speedup vs baseline: 1.1581x; 1.1581x over previous
#include <cuda_runtime.h>
#include <float.h>

#define NATOMS 10000
#define NPAIRS 160000
#define HPITCH 192   // padded h row: [q0(128) | filtered(50) | d(1) | zero pad(13)]

// ---------------- scratch (device globals; no allocation allowed) ----------------
__device__ float g_h[(size_t)NPAIRS * HPITCH];     // edge feature rows
__device__ float g_hidden[(size_t)NPAIRS * 64];
__device__ float g_m[(size_t)NPAIRS * 64];         // q_ij_mtx
__device__ float g_att[(size_t)NPAIRS * 4];
__device__ float g_e[(size_t)NPAIRS * 4];
__device__ float g_comb[(size_t)NPAIRS * 4];       // e / denom[idx_j]
__device__ float g_segmax[NATOMS * 4];
__device__ float g_denom[NATOMS * 4];
__device__ int   g_counts[NATOMS];
__device__ int   g_cursor[NATOMS];
__device__ int   g_offs[NATOMS + 1];
__device__ int   g_order[NPAIRS];
__device__ float g_coeffs[(size_t)NPAIRS * 256];
__device__ float g_norm[(size_t)NATOMS * 256];
__device__ float g_h2[(size_t)NATOMS * 384];       // [q(64) | q_ij(256) | q_comb(64)]
__device__ float g_t1[(size_t)NATOMS * 64];
__device__ float g_t2[(size_t)NATOMS * 64];

// ---------------- helpers ----------------
__device__ __forceinline__ float siluf(float x) { return x / (1.f + __expf(-x)); }
__device__ __forceinline__ float fast_tanh(float x) {
    return 1.f - 2.f / (__expf(2.f * x) + 1.f);
}
__device__ __forceinline__ void atomicMaxFloat(float* a, float v) {
    if (v >= 0.f) atomicMax((int*)a, __float_as_int(v));
    else          atomicMin((unsigned int*)a, __float_as_uint(v));
}
__device__ __forceinline__ unsigned f2tf32(float x) {
    unsigned r;
    asm("cvt.rna.tf32.f32 %0, %1;" : "=r"(r) : "f"(x));
    return r;
}
__device__ __forceinline__ void mma_tf32(float* d, const unsigned* a, const unsigned* b) {
    asm volatile(
        "mma.sync.aligned.m16n8k8.row.col.f32.tf32.tf32.f32 "
        "{%0,%1,%2,%3}, {%4,%5,%6,%7}, {%8,%9}, {%0,%1,%2,%3};"
        : "+f"(d[0]), "+f"(d[1]), "+f"(d[2]), "+f"(d[3])
        : "r"(a[0]), "r"(a[1]), "r"(a[2]), "r"(a[3]), "r"(b[0]), "r"(b[1]));
}

// ---------------- init ----------------
__global__ void k_init() {
    int i = blockIdx.x * blockDim.x + threadIdx.x;
    if (i < NATOMS * 4) { g_segmax[i] = -FLT_MAX; g_denom[i] = 0.f; }
    if (i < NATOMS)     { g_counts[i] = 0; g_cursor[i] = 0; }
}

// ---------------- gather: build q0 | d | zero-pad rows of g_h ----------------
__global__ void k_gather(const float* __restrict__ q, const int* __restrict__ idx_i,
                         const int* __restrict__ idx_j, const float* __restrict__ d_ij) {
    int p    = blockIdx.x * 8 + (threadIdx.x >> 5);
    int lane = threadIdx.x & 31;
    int i = idx_i[p], j = idx_j[p];
    float* hr = g_h + (size_t)p * HPITCH;
    const float* qi = q + (size_t)i * 64;
    const float* qj = q + (size_t)j * 64;
    hr[lane]      = qi[lane];       hr[32 + lane] = qi[32 + lane];
    hr[64 + lane] = qj[lane];       hr[96 + lane] = qj[32 + lane];
    if (lane < 14) hr[178 + lane] = (lane == 0) ? d_ij[p] : 0.f;
}

// ================= edge MLP GEMMs on tensor cores (tf32 mma.sync) =================
// Block tile 128M x 64N, BK=32; 8 warps (4x2); warp tile 32x32; acc d[2][4][4].
// MODE 0: h[:, :128] @ w_in^T  (K=128, N=50), epi rbf*(.)  -> g_h cols 128..177
// MODE 1: h @ w_out1^T (K=192 zero-padded, N=64), silu     -> g_hidden
// MODE 2: hidden @ w_out2^T (K=64, N=64), +bias            -> g_m
#define MMP 36   // smem k pitch (words): conflict-free fragment gathers
template <int MODE>
__global__ void __launch_bounds__(256, 2)
k_edge_mma(const float* __restrict__ W, const float* __restrict__ bias,
           const float* __restrict__ d_ij, const float* __restrict__ roffs,
           const float* __restrict__ rwids) {
    constexpr int KCH = (MODE == 0) ? 4 : (MODE == 1) ? 6 : 2;   // chunks of 32
    constexpr int KW  = (MODE == 0) ? 128 : (MODE == 1) ? 179 : 64;  // real W stride
    constexpr int NW  = (MODE == 0) ? 50 : 64;
    constexpr int LDA = (MODE <= 1) ? HPITCH : 64;
    constexpr int LDC = (MODE == 0) ? HPITCH : 64;

    const float* A = (MODE == 2) ? g_hidden : g_h;
    float* C = (MODE == 0) ? (g_h + 128) : (MODE == 1) ? g_hidden : g_m;

    __shared__ unsigned sA[128 * MMP];   // [m][k] tf32 bits
    __shared__ unsigned sB[64 * MMP];    // [n][k] tf32 bits

    const int t    = threadIdx.x;
    const int lane = t & 31;
    const int warp = t >> 5;
    const int gid  = lane >> 2;
    const int tig  = lane & 3;
    const int warpM = warp & 3;          // 0..3 -> 32 rows each
    const int warpN = warp >> 2;         // 0..1 -> 32 cols each
    const int p0 = blockIdx.x * 128;

    // A staging: 2 threads/row, 16 floats each
    const int srow  = t >> 1;            // 0..127
    const int shalf = t & 1;
    // B staging: 4 threads/row, 8 floats each
    const int brow = t >> 2;             // 0..63
    const int bq   = t & 3;

    float d[2][4][4];
#pragma unroll
    for (int mt = 0; mt < 2; mt++)
#pragma unroll
        for (int nf = 0; nf < 4; nf++)
#pragma unroll
            for (int v = 0; v < 4; v++) d[mt][nf][v] = 0.f;

    float4 pa[4];
    float  pw[8];

    // ---- prefetch chunk 0 ----
    {
        const float* ap = A + (size_t)(p0 + srow) * LDA + shalf * 16;
#pragma unroll
        for (int i = 0; i < 4; i++)
            pa[i] = *reinterpret_cast<const float4*>(ap + i * 4);
#pragma unroll
        for (int j = 0; j < 8; j++) {
            int k = bq * 8 + j;
            bool ok = true;
            if constexpr (NW < 64) ok = (brow < NW);
            if constexpr ((KW & 31) != 0) ok = ok && (k < KW);
            pw[j] = ok ? __ldg(&W[(size_t)brow * KW + k]) : 0.f;
        }
    }

    for (int kc = 0; kc < KCH; kc++) {
        __syncthreads();
        // ---- store staged chunk ----
        {
            unsigned* ap = &sA[srow * MMP + shalf * 16];
            const float av[16] = {pa[0].x, pa[0].y, pa[0].z, pa[0].w,
                                  pa[1].x, pa[1].y, pa[1].z, pa[1].w,
                                  pa[2].x, pa[2].y, pa[2].z, pa[2].w,
                                  pa[3].x, pa[3].y, pa[3].z, pa[3].w};
#pragma unroll
            for (int i = 0; i < 16; i++) ap[i] = f2tf32(av[i]);
            unsigned* bp = &sB[brow * MMP + bq * 8];
#pragma unroll
            for (int j = 0; j < 8; j++) bp[j] = f2tf32(pw[j]);
        }
        __syncthreads();

        // ---- prefetch next chunk ----
        if (kc + 1 < KCH) {
            int k0 = (kc + 1) * 32;
            const float* ap = A + (size_t)(p0 + srow) * LDA + k0 + shalf * 16;
#pragma unroll
            for (int i = 0; i < 4; i++)
                pa[i] = *reinterpret_cast<const float4*>(ap + i * 4);
#pragma unroll
            for (int j = 0; j < 8; j++) {
                int k = k0 + bq * 8 + j;
                bool ok = true;
                if constexpr (NW < 64) ok = (brow < NW);
                if constexpr ((KW & 31) != 0) ok = ok && (k < KW);
                pw[j] = ok ? __ldg(&W[(size_t)brow * KW + k]) : 0.f;
            }
        }

        // ---- compute: 4 k-steps of 8 ----
#pragma unroll
        for (int ks = 0; ks < 4; ks++) {
            const int kb = ks * 8;
            unsigned a[2][4];
#pragma unroll
            for (int mt = 0; mt < 2; mt++) {
                const int mb = warpM * 32 + mt * 16;
                a[mt][0] = sA[(mb + gid) * MMP + kb + tig];
                a[mt][1] = sA[(mb + gid + 8) * MMP + kb + tig];
                a[mt][2] = sA[(mb + gid) * MMP + kb + tig + 4];
                a[mt][3] = sA[(mb + gid + 8) * MMP + kb + tig + 4];
            }
#pragma unroll
            for (int nf = 0; nf < 4; nf++) {
                unsigned b[2];
                const int nb = warpN * 32 + nf * 8 + gid;
                b[0] = sB[nb * MMP + kb + tig];
                b[1] = sB[nb * MMP + kb + tig + 4];
                mma_tf32(d[0][nf], a[0], b);
                mma_tf32(d[1][nf], a[1], b);
            }
        }
    }

    // ---- epilogue ----
#pragma unroll
    for (int mt = 0; mt < 2; mt++) {
        const int prow = p0 + warpM * 32 + mt * 16 + gid;   // and prow+8
        if constexpr (MODE == 0) {
            float dv0 = __ldg(&d_ij[prow]);
            float dv1 = __ldg(&d_ij[prow + 8]);
#pragma unroll
            for (int nf = 0; nf < 4; nf++) {
                const int col = warpN * 32 + nf * 8 + tig * 2;
#pragma unroll
                for (int u = 0; u < 2; u++) {
                    int gn = col + u;
                    if (gn < 50) {
                        float off = __ldg(&roffs[gn]), wd = __ldg(&rwids[gn]);
                        float bs  = __ldg(&bias[gn]);
                        float cf  = -0.5f / (wd * wd);
                        float dd0 = dv0 - off, dd1 = dv1 - off;
                        C[(size_t)prow * LDC + gn] =
                            __expf(cf * dd0 * dd0) * (d[mt][nf][u] + bs);
                        C[(size_t)(prow + 8) * LDC + gn] =
                            __expf(cf * dd1 * dd1) * (d[mt][nf][2 + u] + bs);
                    }
                }
            }
        } else {
#pragma unroll
            for (int nf = 0; nf < 4; nf++) {
                const int col = warpN * 32 + nf * 8 + tig * 2;
                float b0 = __ldg(&bias[col]), b1 = __ldg(&bias[col + 1]);
                float2 lo, hi;
                if constexpr (MODE == 2) {
                    lo.x = d[mt][nf][0] + b0; lo.y = d[mt][nf][1] + b1;
                    hi.x = d[mt][nf][2] + b0; hi.y = d[mt][nf][3] + b1;
                } else {
                    lo.x = siluf(d[mt][nf][0] + b0); lo.y = siluf(d[mt][nf][1] + b1);
                    hi.x = siluf(d[mt][nf][2] + b0); hi.y = siluf(d[mt][nf][3] + b1);
                }
                *reinterpret_cast<float2*>(&C[(size_t)prow * LDC + col]) = lo;
                *reinterpret_cast<float2*>(&C[(size_t)(prow + 8) * LDC + col]) = hi;
            }
        }
    }
}

// ================= mixing GEMM on tensor cores (tf32 mma.sync) =================
// C[p, n] = tanh( sum_k A[p,k] * w_mix[n,k] ),  A[p,k] = m[p,k>>2]*comb[p,k&3]
__global__ void __launch_bounds__(256, 2)
k_mix_mma(const float* __restrict__ W) {
    __shared__ unsigned sA[128 * MMP];   // [m][k] tf32 bits
    __shared__ unsigned sB[128 * MMP];   // [n][k] tf32 bits

    const int t    = threadIdx.x;
    const int lane = t & 31;
    const int warp = t >> 5;
    const int gid  = lane >> 2;
    const int tig  = lane & 3;
    const int warpM = warp & 3;        // 0..3  -> 32 rows each
    const int warpN = warp >> 2;       // 0..1  -> 64 cols each
    const int p0 = blockIdx.x * 128;
    const int n0 = blockIdx.y * 128;

    const int srow = t >> 1;           // 0..127
    const int shalf = t & 1;

    const float4 cb = *reinterpret_cast<const float4*>(&g_comb[(size_t)(p0 + srow) * 4]);
    const float cbv[4] = {cb.x, cb.y, cb.z, cb.w};

    float d[2][8][4];
#pragma unroll
    for (int mt = 0; mt < 2; mt++)
#pragma unroll
        for (int nf = 0; nf < 8; nf++)
#pragma unroll
            for (int v = 0; v < 4; v++) d[mt][nf][v] = 0.f;

    float4 pmv;
    float4 pwv[4];

    pmv = *reinterpret_cast<const float4*>(&g_m[(size_t)(p0 + srow) * 64 + shalf * 4]);
#pragma unroll
    for (int i = 0; i < 4; i++)
        pwv[i] = *reinterpret_cast<const float4*>(
            &W[(size_t)(n0 + srow) * 256 + shalf * 16 + i * 4]);

    for (int kc = 0; kc < 8; kc++) {
        __syncthreads();
        {
            const float mv[4] = {pmv.x, pmv.y, pmv.z, pmv.w};
            unsigned* ap = &sA[srow * MMP + shalf * 16];
#pragma unroll
            for (int i = 0; i < 4; i++)
#pragma unroll
                for (int j = 0; j < 4; j++)
                    ap[i * 4 + j] = f2tf32(mv[i] * cbv[j]);
            unsigned* bp = &sB[srow * MMP + shalf * 16];
            const float wv[16] = {pwv[0].x, pwv[0].y, pwv[0].z, pwv[0].w,
                                  pwv[1].x, pwv[1].y, pwv[1].z, pwv[1].w,
                                  pwv[2].x, pwv[2].y, pwv[2].z, pwv[2].w,
                                  pwv[3].x, pwv[3].y, pwv[3].z, pwv[3].w};
#pragma unroll
            for (int i = 0; i < 16; i++) bp[i] = f2tf32(wv[i]);
        }
        __syncthreads();

        if (kc + 1 < 8) {
            int k0 = (kc + 1) * 32;
            pmv = *reinterpret_cast<const float4*>(
                &g_m[(size_t)(p0 + srow) * 64 + (k0 >> 2) + shalf * 4]);
#pragma unroll
            for (int i = 0; i < 4; i++)
                pwv[i] = *reinterpret_cast<const float4*>(
                    &W[(size_t)(n0 + srow) * 256 + k0 + shalf * 16 + i * 4]);
        }

#pragma unroll
        for (int ks = 0; ks < 4; ks++) {
            const int kb = ks * 8;
            unsigned a[2][4];
#pragma unroll
            for (int mt = 0; mt < 2; mt++) {
                const int mb = warpM * 32 + mt * 16;
                a[mt][0] = sA[(mb + gid) * MMP + kb + tig];
                a[mt][1] = sA[(mb + gid + 8) * MMP + kb + tig];
                a[mt][2] = sA[(mb + gid) * MMP + kb + tig + 4];
                a[mt][3] = sA[(mb + gid + 8) * MMP + kb + tig + 4];
            }
#pragma unroll
            for (int nf = 0; nf < 8; nf++) {
                unsigned b[2];
                const int nb = warpN * 64 + nf * 8 + gid;
                b[0] = sB[nb * MMP + kb + tig];
                b[1] = sB[nb * MMP + kb + tig + 4];
                mma_tf32(d[0][nf], a[0], b);
                mma_tf32(d[1][nf], a[1], b);
            }
        }
    }

#pragma unroll
    for (int mt = 0; mt < 2; mt++) {
        const int prow = p0 + warpM * 32 + mt * 16 + gid;
#pragma unroll
        for (int nf = 0; nf < 8; nf++) {
            const int col = n0 + warpN * 64 + nf * 8 + tig * 2;
            float2 lo, hi;
            lo.x = fast_tanh(d[mt][nf][0]); lo.y = fast_tanh(d[mt][nf][1]);
            hi.x = fast_tanh(d[mt][nf][2]); hi.y = fast_tanh(d[mt][nf][3]);
            *reinterpret_cast<float2*>(&g_coeffs[(size_t)prow * 256 + col]) = lo;
            *reinterpret_cast<float2*>(&g_coeffs[(size_t)(prow + 8) * 256 + col]) = hi;
        }
    }
}

// ================= atom-level GEMM (small M): 64x64 tiles =================
// MODE 4: norm @ w_post1^T, silu -> g_t1
// MODE 5: t1 @ w_post2^T, silu -> g_h2[:, 320:384]
// MODE 6: h2 @ w_node1^T, silu -> g_t2
// MODE 7: t2 @ w_node2^T, q + silu(.) -> out
template <int MODE>
__global__ void k_gemm(const float* __restrict__ W, const float* __restrict__ bias,
                       const float* __restrict__ x1, float* __restrict__ outp) {
    constexpr int M  = NATOMS;
    constexpr int KT = (MODE == 4) ? 16 : (MODE == 5) ? 4 : (MODE == 6) ? 24 : 4;
    constexpr int KW = (MODE == 4) ? 256 : (MODE == 5) ? 64 : (MODE == 6) ? 384 : 64;
    constexpr int LDA = (MODE == 4) ? 256 : (MODE == 6) ? 384 : 64;
    constexpr int LDC = (MODE == 5) ? 384 : 64;

    const float* A;
    float* C;
    if constexpr (MODE == 4)      { A = g_norm;   C = g_t1;      }
    else if constexpr (MODE == 5) { A = g_t1;     C = g_h2 + 320;}
    else if constexpr (MODE == 6) { A = g_h2;     C = g_t2;      }
    else                          { A = g_t2;     C = outp;      }

    __shared__ __align__(16) float sA[16 * 68];
    __shared__ __align__(16) float sW[16 * 68];

    int t  = threadIdx.x;
    int p0 = blockIdx.x * 64;
    int tx = t & 15, ty = t >> 4;
    int am   = t >> 2;
    int ak   = (t & 3) * 4;
    int arow = p0 + am;

    float acc[4][4];
#pragma unroll
    for (int i = 0; i < 4; i++)
#pragma unroll
        for (int j = 0; j < 4; j++) acc[i][j] = 0.f;

    for (int kt = 0; kt < KT; kt++) {
        int k0 = kt * 16;
        float4 av = make_float4(0.f, 0.f, 0.f, 0.f);
        if (arow < M)
            av = *reinterpret_cast<const float4*>(A + (size_t)arow * LDA + k0 + ak);
        float wv[4];
#pragma unroll
        for (int j = 0; j < 4; j++) {
            int k = k0 + ak + j;
            wv[j] = (k < KW) ? __ldg(&W[(size_t)am * KW + k]) : 0.f;
        }
        __syncthreads();
        sA[(ak + 0) * 68 + am] = av.x; sA[(ak + 1) * 68 + am] = av.y;
        sA[(ak + 2) * 68 + am] = av.z; sA[(ak + 3) * 68 + am] = av.w;
#pragma unroll
        for (int j = 0; j < 4; j++) sW[(ak + j) * 68 + am] = wv[j];
        __syncthreads();
#pragma unroll
        for (int kk = 0; kk < 16; kk++) {
            float4 a = *reinterpret_cast<const float4*>(&sA[kk * 68 + ty * 4]);
            float4 b = *reinterpret_cast<const float4*>(&sW[kk * 68 + tx * 4]);
            acc[0][0] += a.x * b.x; acc[0][1] += a.x * b.y; acc[0][2] += a.x * b.z; acc[0][3] += a.x * b.w;
            acc[1][0] += a.y * b.x; acc[1][1] += a.y * b.y; acc[1][2] += a.y * b.z; acc[1][3] += a.y * b.w;
            acc[2][0] += a.z * b.x; acc[2][1] += a.z * b.y; acc[2][2] += a.z * b.z; acc[2][3] += a.z * b.w;
            acc[3][0] += a.w * b.x; acc[3][1] += a.w * b.y; acc[3][2] += a.w * b.z; acc[3][3] += a.w * b.w;
        }
    }

#pragma unroll
    for (int i = 0; i < 4; i++) {
        int p = p0 + ty * 4 + i;
        if (p >= M) continue;
#pragma unroll
        for (int j = 0; j < 4; j++) {
            int gn = tx * 4 + j;
            float v = acc[i][j];
            if constexpr (MODE == 7) {
                C[(size_t)p * LDC + gn] = x1[(size_t)p * 64 + gn] + siluf(v + bias[gn]);
            } else {
                C[(size_t)p * LDC + gn] = siluf(v + bias[gn]);
            }
        }
    }
}

// ---------------- attention logits + segment max + degree counts ----------------
__global__ void k_att(const float* __restrict__ w_att, const float* __restrict__ b_att,
                      const int* __restrict__ idx_j) {
    int p    = blockIdx.x * 8 + (threadIdx.x >> 5);
    int lane = threadIdx.x & 31;
    const float* mr = g_m + (size_t)p * 64;
    float m1 = mr[lane], m2 = mr[32 + lane];
    float pa[4];
#pragma unroll
    for (int a = 0; a < 4; a++)
        pa[a] = __ldg(&w_att[a * 64 + lane]) * m1 + __ldg(&w_att[a * 64 + 32 + lane]) * m2;
#pragma unroll
    for (int o = 16; o > 0; o >>= 1)
#pragma unroll
        for (int a = 0; a < 4; a++) pa[a] += __shfl_xor_sync(0xffffffffu, pa[a], o);
    if (lane == 0) {
        int j = idx_j[p];
#pragma unroll
        for (int a = 0; a < 4; a++) {
            float v = pa[a] + b_att[a];
            v = (v >= 0.f) ? v : 2.f * expm1f(0.5f * v);   // celu alpha=2
            g_att[p * 4 + a] = v;
            atomicMaxFloat(&g_segmax[j * 4 + a], v);
        }
        atomicAdd(&g_counts[j], 1);
    }
}

// ---------------- softmax numerators + denominators ----------------
__global__ void k_exp(const int* __restrict__ idx_j) {
    int p = blockIdx.x * blockDim.x + threadIdx.x;
    if (p >= NPAIRS) return;
    int j = idx_j[p];
#pragma unroll
    for (int a = 0; a < 4; a++) {
        float v = __expf(g_att[p * 4 + a] - g_segmax[j * 4 + a]);
        g_e[p * 4 + a] = v;
        atomicAdd(&g_denom[j * 4 + a], v);
    }
}

// ---------------- comb = e / denom[idx_j] ----------------
__global__ void k_comb(const int* __restrict__ idx_j) {
    int p = blockIdx.x * blockDim.x + threadIdx.x;
    if (p >= NPAIRS) return;
    int j = idx_j[p];
    float4 e4 = *reinterpret_cast<const float4*>(&g_e[(size_t)p * 4]);
    float4 d4 = *reinterpret_cast<const float4*>(&g_denom[(size_t)j * 4]);
    float4 c4 = make_float4(e4.x / d4.x, e4.y / d4.y, e4.z / d4.z, e4.w / d4.w);
    *reinterpret_cast<float4*>(&g_comb[(size_t)p * 4]) = c4;
}

// ---------------- exclusive scan of counts -> offs (single block) ----------------
__global__ void k_scan() {
    __shared__ int part[1024];
    int tid = threadIdx.x;
    int base = tid * 10;
    int loc[10];
    int s = 0;
#pragma unroll
    for (int j = 0; j < 10; j++) {
        int idx = base + j;
        int v = (idx < NATOMS) ? g_counts[idx] : 0;
        loc[j] = s; s += v;
    }
    part[tid] = s;
    __syncthreads();
    for (int off = 1; off < 1024; off <<= 1) {
        int v = (tid >= off) ? part[tid - off] : 0;
        __syncthreads();
        part[tid] += v;
        __syncthreads();
    }
    int pre = (tid > 0) ? part[tid - 1] : 0;
#pragma unroll
    for (int j = 0; j < 10; j++) {
        int idx = base + j;
        if (idx < NATOMS) g_offs[idx] = pre + loc[j];
    }
    if (tid == 1023) g_offs[NATOMS] = part[1023];
}

// ---------------- fill CSR edge order ----------------
__global__ void k_fill(const int* __restrict__ idx_j) {
    int p = blockIdx.x * blockDim.x + threadIdx.x;
    if (p >= NPAIRS) return;
    int j = idx_j[p];
    int pos = atomicAdd(&g_cursor[j], 1);
    g_order[g_offs[j] + pos] = p;
}

// ---------------- per-atom gather reductions: q_ij, norm; also copy q into h2 ----
__global__ void k_segreduce(const float* __restrict__ q, const float* __restrict__ r_ij,
                            const float* __restrict__ d_ij) {
    int n    = blockIdx.x * 8 + (threadIdx.x >> 5);
    int lane = threadIdx.x & 31;
    if (n >= NATOMS) return;
    int beg = g_offs[n], end = g_offs[n + 1];
    int cnt = end - beg;
    float inv = 1.f / (float)max(cnt, 1);
    g_h2[(size_t)n * 384 + lane]      = q[(size_t)n * 64 + lane];
    g_h2[(size_t)n * 384 + 32 + lane] = q[(size_t)n * 64 + 32 + lane];
    for (int cr = 0; cr < 8; cr++) {
        int c = cr * 32 + lane;
        int f = c >> 2, hh = c & 3;
        float ax = 0.f, ay = 0.f, az = 0.f, aq = 0.f;
        for (int tt = beg; tt < end; tt++) {
            int p = g_order[tt];
            float co   = __ldg(&g_coeffs[(size_t)p * 256 + c]);
            float rinv = 1.f / (__ldg(&d_ij[p]) + 1e-5f);
            ax += co * __ldg(&r_ij[p * 3 + 0]) * rinv;
            ay += co * __ldg(&r_ij[p * 3 + 1]) * rinv;
            az += co * __ldg(&r_ij[p * 3 + 2]) * rinv;
            aq += __ldg(&g_m[(size_t)p * 64 + f]) * __ldg(&g_comb[p * 4 + hh]);
        }
        float mx = ax * inv, my = ay * inv, mz = az * inv;
        g_norm[(size_t)n * 256 + c]     = mx * mx + my * my + mz * mz;
        g_h2[(size_t)n * 384 + 64 + c]  = aq;
    }
}

// ---------------- launch ----------------
extern "C" void kernel_launch(void* const* d_in, const int* in_sizes, int n_in,
                              void* d_out, int out_size) {
    (void)in_sizes; (void)n_in; (void)out_size;
    const float* q       = (const float*)d_in[0];
    const float* r_ij    = (const float*)d_in[2];
    const float* d_ij    = (const float*)d_in[3];
    const int*   idx_i   = (const int*)d_in[4];
    const int*   idx_j   = (const int*)d_in[5];
    const float* rbf_off = (const float*)d_in[6];
    const float* rbf_w   = (const float*)d_in[7];
    const float* w_in    = (const float*)d_in[8];
    const float* b_in    = (const float*)d_in[9];
    const float* w_out1  = (const float*)d_in[10];
    const float* b_out1  = (const float*)d_in[11];
    const float* w_out2  = (const float*)d_in[12];
    const float* b_out2  = (const float*)d_in[13];
    const float* w_att   = (const float*)d_in[14];
    const float* b_att   = (const float*)d_in[15];
    const float* w_mix   = (const float*)d_in[16];
    const float* w_post1 = (const float*)d_in[17];
    const float* b_post1 = (const float*)d_in[18];
    const float* w_post2 = (const float*)d_in[19];
    const float* b_post2 = (const float*)d_in[20];
    const float* w_node1 = (const float*)d_in[21];
    const float* b_node1 = (const float*)d_in[22];
    const float* w_node2 = (const float*)d_in[23];
    const float* b_node2 = (const float*)d_in[24];
    float* out = (float*)d_out;

    k_init<<<157, 256>>>();
    k_gather<<<NPAIRS / 8, 256>>>(q, idx_i, idx_j, d_ij);
    k_edge_mma<0><<<NPAIRS / 128, 256>>>(w_in, b_in, d_ij, rbf_off, rbf_w);
    k_edge_mma<1><<<NPAIRS / 128, 256>>>(w_out1, b_out1, nullptr, nullptr, nullptr);
    k_edge_mma<2><<<NPAIRS / 128, 256>>>(w_out2, b_out2, nullptr, nullptr, nullptr);
    k_att<<<NPAIRS / 8, 256>>>(w_att, b_att, idx_j);
    k_exp<<<(NPAIRS + 255) / 256, 256>>>(idx_j);
    k_comb<<<(NPAIRS + 255) / 256, 256>>>(idx_j);
    k_scan<<<1, 1024>>>();
    k_fill<<<(NPAIRS + 255) / 256, 256>>>(idx_j);
    k_mix_mma<<<dim3(NPAIRS / 128, 2), 256>>>(w_mix);
    k_segreduce<<<NATOMS / 8, 256>>>(q, r_ij, d_ij);
    k_gemm<4><<<157, 256>>>(w_post1, b_post1, nullptr, nullptr);
    k_gemm<5><<<157, 256>>>(w_post2, b_post2, nullptr, nullptr);
    k_gemm<6><<<157, 256>>>(w_node1, b_node1, nullptr, nullptr);
    k_gemm<7><<<157, 256>>>(w_node2, b_node2, q, out);
}

// round 17
// speedup vs baseline: 1.3126x; 1.1334x over previous
#include <cuda_runtime.h>
#include <float.h>

#define NATOMS 10000
#define NPAIRS 160000
#define HPITCH 192   // padded h row: [q0(128) | filtered(50) | d(1) | zero pad(13)]

// ---------------- scratch (device globals; no allocation allowed) ----------------
__device__ unsigned g_h[(size_t)NPAIRS * HPITCH];  // edge features, tf32 bit patterns
__device__ unsigned g_hidden[(size_t)NPAIRS * 64]; // hidden, tf32 bit patterns
__device__ float g_m[(size_t)NPAIRS * 64];         // q_ij_mtx (fp32)
__device__ float g_att[(size_t)NPAIRS * 4];
__device__ float g_e[(size_t)NPAIRS * 4];
__device__ float g_comb[(size_t)NPAIRS * 4];       // e / denom[idx_j]
__device__ float g_segmax[NATOMS * 4];
__device__ float g_denom[NATOMS * 4];
__device__ int   g_counts[NATOMS];
__device__ int   g_cursor[NATOMS];
__device__ int   g_offs[NATOMS + 1];
__device__ int   g_order[NPAIRS];
__device__ float g_coeffs[(size_t)NPAIRS * 256];
__device__ float g_norm[(size_t)NATOMS * 256];
__device__ float g_h2[(size_t)NATOMS * 384];       // [q(64) | q_ij(256) | q_comb(64)]
__device__ float g_t1[(size_t)NATOMS * 64];
__device__ float g_t2[(size_t)NATOMS * 64];
// pre-converted tf32 weights (zero-padded)
__device__ unsigned g_wA[64 * 128];                // w_in   (50x128 -> 64x128)
__device__ unsigned g_wB[64 * 192];                // w_out1 (64x179 -> 64x192)
__device__ unsigned g_wC[64 * 64];                 // w_out2
__device__ unsigned g_wD[256 * 256];               // w_mix

// ---------------- helpers ----------------
__device__ __forceinline__ float siluf(float x) { return x / (1.f + __expf(-x)); }
__device__ __forceinline__ float fast_tanh(float x) {
    return 1.f - 2.f / (__expf(2.f * x) + 1.f);
}
__device__ __forceinline__ void atomicMaxFloat(float* a, float v) {
    if (v >= 0.f) atomicMax((int*)a, __float_as_int(v));
    else          atomicMin((unsigned int*)a, __float_as_uint(v));
}
__device__ __forceinline__ unsigned f2tf32(float x) {
    unsigned r;
    asm("cvt.rna.tf32.f32 %0, %1;" : "=r"(r) : "f"(x));
    return r;
}
__device__ __forceinline__ void mma_tf32(float* d, const unsigned* a, const unsigned* b) {
    asm volatile(
        "mma.sync.aligned.m16n8k8.row.col.f32.tf32.tf32.f32 "
        "{%0,%1,%2,%3}, {%4,%5,%6,%7}, {%8,%9}, {%0,%1,%2,%3};"
        : "+f"(d[0]), "+f"(d[1]), "+f"(d[2]), "+f"(d[3])
        : "r"(a[0]), "r"(a[1]), "r"(a[2]), "r"(a[3]), "r"(b[0]), "r"(b[1]));
}

// ---------------- init ----------------
__global__ void k_init() {
    int i = blockIdx.x * blockDim.x + threadIdx.x;
    if (i < NATOMS * 4) { g_segmax[i] = -FLT_MAX; g_denom[i] = 0.f; }
    if (i < NATOMS)     { g_counts[i] = 0; g_cursor[i] = 0; }
}

// ---------------- weight pre-conversion: fp32 -> padded tf32 bits ----------------
__global__ void k_cvtw(const float* __restrict__ src, unsigned* __restrict__ dst,
                       int srcRows, int srcK, int dstK, int total) {
    int i = blockIdx.x * 256 + threadIdx.x;
    if (i >= total) return;
    int r = i / dstK, k = i - r * dstK;
    float v = (r < srcRows && k < srcK) ? src[r * srcK + k] : 0.f;
    dst[i] = f2tf32(v);
}

// ---------------- gather: build q0 | d | zero-pad rows of g_h (tf32 bits) -------
__global__ void k_gather(const float* __restrict__ q, const int* __restrict__ idx_i,
                         const int* __restrict__ idx_j, const float* __restrict__ d_ij) {
    int p    = blockIdx.x * 8 + (threadIdx.x >> 5);
    int lane = threadIdx.x & 31;
    int i = idx_i[p], j = idx_j[p];
    unsigned* hr = g_h + (size_t)p * HPITCH;
    const float* qi = q + (size_t)i * 64;
    const float* qj = q + (size_t)j * 64;
    hr[lane]      = f2tf32(qi[lane]);       hr[32 + lane] = f2tf32(qi[32 + lane]);
    hr[64 + lane] = f2tf32(qj[lane]);       hr[96 + lane] = f2tf32(qj[32 + lane]);
    if (lane < 14) hr[178 + lane] = (lane == 0) ? f2tf32(d_ij[p]) : 0u;
}

// ================= edge MLP GEMMs on tensor cores (tf32 mma.sync) =================
// Block tile 128M x 64N, BK=32; 8 warps (4x2); warp tile 32x32; acc d[2][4][4].
// All operands pre-converted tf32 bits -> staging is pure uint4 LDG/STS.
// MODE 0: h[:, :128] @ w_in^T  (K=128, N=50), epi rbf*(.)  -> g_h cols 128..177 (tf32)
// MODE 1: h @ w_out1^T (K=192, N=64), silu                 -> g_hidden (tf32)
// MODE 2: hidden @ w_out2^T (K=64, N=64), +bias            -> g_m (fp32)
#define MMP 36   // smem k pitch (words): conflict-free fragment gathers
template <int MODE>
__global__ void __launch_bounds__(256, 2)
k_edge_mma(const float* __restrict__ bias, const float* __restrict__ d_ij,
           const float* __restrict__ roffs, const float* __restrict__ rwids) {
    constexpr int KCH = (MODE == 0) ? 4 : (MODE == 1) ? 6 : 2;   // chunks of 32
    constexpr int KP  = (MODE == 0) ? 128 : (MODE == 1) ? 192 : 64; // padded W stride
    constexpr int LDA = (MODE <= 1) ? HPITCH : 64;
    constexpr int LDC = (MODE == 0) ? HPITCH : 64;

    const unsigned* A  = (MODE == 2) ? g_hidden : g_h;
    const unsigned* Wp = (MODE == 0) ? g_wA : (MODE == 1) ? g_wB : g_wC;

    __shared__ unsigned sA[128 * MMP];   // [m][k] tf32 bits
    __shared__ unsigned sB[64 * MMP];    // [n][k] tf32 bits

    const int t    = threadIdx.x;
    const int lane = t & 31;
    const int warp = t >> 5;
    const int gid  = lane >> 2;
    const int tig  = lane & 3;
    const int warpM = warp & 3;          // 0..3 -> 32 rows each
    const int warpN = warp >> 2;         // 0..1 -> 32 cols each
    const int p0 = blockIdx.x * 128;

    // A staging: 2 threads/row, 16 words each
    const int srow  = t >> 1;            // 0..127
    const int shalf = t & 1;
    // B staging: 4 threads/row, 8 words each
    const int brow = t >> 2;             // 0..63
    const int bq   = t & 3;

    float d[2][4][4];
#pragma unroll
    for (int mt = 0; mt < 2; mt++)
#pragma unroll
        for (int nf = 0; nf < 4; nf++)
#pragma unroll
            for (int v = 0; v < 4; v++) d[mt][nf][v] = 0.f;

    uint4 pa[4];
    uint4 pb[2];

    // ---- prefetch chunk 0 ----
    {
        const unsigned* ap = A + (size_t)(p0 + srow) * LDA + shalf * 16;
#pragma unroll
        for (int i = 0; i < 4; i++)
            pa[i] = *reinterpret_cast<const uint4*>(ap + i * 4);
        const unsigned* bp = Wp + (size_t)brow * KP + bq * 8;
        pb[0] = *reinterpret_cast<const uint4*>(bp);
        pb[1] = *reinterpret_cast<const uint4*>(bp + 4);
    }

    for (int kc = 0; kc < KCH; kc++) {
        __syncthreads();
        // ---- store staged chunk (pure vector STS) ----
        {
            uint4* ap = reinterpret_cast<uint4*>(&sA[srow * MMP + shalf * 16]);
            ap[0] = pa[0]; ap[1] = pa[1]; ap[2] = pa[2]; ap[3] = pa[3];
            uint4* bp = reinterpret_cast<uint4*>(&sB[brow * MMP + bq * 8]);
            bp[0] = pb[0]; bp[1] = pb[1];
        }
        __syncthreads();

        // ---- prefetch next chunk ----
        if (kc + 1 < KCH) {
            int k0 = (kc + 1) * 32;
            const unsigned* ap = A + (size_t)(p0 + srow) * LDA + k0 + shalf * 16;
#pragma unroll
            for (int i = 0; i < 4; i++)
                pa[i] = *reinterpret_cast<const uint4*>(ap + i * 4);
            const unsigned* bp = Wp + (size_t)brow * KP + k0 + bq * 8;
            pb[0] = *reinterpret_cast<const uint4*>(bp);
            pb[1] = *reinterpret_cast<const uint4*>(bp + 4);
        }

        // ---- compute: 4 k-steps of 8 ----
#pragma unroll
        for (int ks = 0; ks < 4; ks++) {
            const int kb = ks * 8;
            unsigned a[2][4];
#pragma unroll
            for (int mt = 0; mt < 2; mt++) {
                const int mb = warpM * 32 + mt * 16;
                a[mt][0] = sA[(mb + gid) * MMP + kb + tig];
                a[mt][1] = sA[(mb + gid + 8) * MMP + kb + tig];
                a[mt][2] = sA[(mb + gid) * MMP + kb + tig + 4];
                a[mt][3] = sA[(mb + gid + 8) * MMP + kb + tig + 4];
            }
#pragma unroll
            for (int nf = 0; nf < 4; nf++) {
                unsigned b[2];
                const int nb = warpN * 32 + nf * 8 + gid;
                b[0] = sB[nb * MMP + kb + tig];
                b[1] = sB[nb * MMP + kb + tig + 4];
                mma_tf32(d[0][nf], a[0], b);
                mma_tf32(d[1][nf], a[1], b);
            }
        }
    }

    // ---- epilogue ----
#pragma unroll
    for (int mt = 0; mt < 2; mt++) {
        const int prow = p0 + warpM * 32 + mt * 16 + gid;   // and prow+8
        if constexpr (MODE == 0) {
            unsigned* C = g_h + 128;
            float dv0 = __ldg(&d_ij[prow]);
            float dv1 = __ldg(&d_ij[prow + 8]);
#pragma unroll
            for (int nf = 0; nf < 4; nf++) {
                const int col = warpN * 32 + nf * 8 + tig * 2;
#pragma unroll
                for (int u = 0; u < 2; u++) {
                    int gn = col + u;
                    if (gn < 50) {
                        float off = __ldg(&roffs[gn]), wd = __ldg(&rwids[gn]);
                        float bs  = __ldg(&bias[gn]);
                        float cf  = -0.5f / (wd * wd);
                        float dd0 = dv0 - off, dd1 = dv1 - off;
                        C[(size_t)prow * LDC + gn] =
                            f2tf32(__expf(cf * dd0 * dd0) * (d[mt][nf][u] + bs));
                        C[(size_t)(prow + 8) * LDC + gn] =
                            f2tf32(__expf(cf * dd1 * dd1) * (d[mt][nf][2 + u] + bs));
                    }
                }
            }
        } else if constexpr (MODE == 1) {
#pragma unroll
            for (int nf = 0; nf < 4; nf++) {
                const int col = warpN * 32 + nf * 8 + tig * 2;
                float b0 = __ldg(&bias[col]), b1 = __ldg(&bias[col + 1]);
                uint2 lo, hi;
                lo.x = f2tf32(siluf(d[mt][nf][0] + b0));
                lo.y = f2tf32(siluf(d[mt][nf][1] + b1));
                hi.x = f2tf32(siluf(d[mt][nf][2] + b0));
                hi.y = f2tf32(siluf(d[mt][nf][3] + b1));
                *reinterpret_cast<uint2*>(&g_hidden[(size_t)prow * 64 + col]) = lo;
                *reinterpret_cast<uint2*>(&g_hidden[(size_t)(prow + 8) * 64 + col]) = hi;
            }
        } else {
#pragma unroll
            for (int nf = 0; nf < 4; nf++) {
                const int col = warpN * 32 + nf * 8 + tig * 2;
                float b0 = __ldg(&bias[col]), b1 = __ldg(&bias[col + 1]);
                float2 lo, hi;
                lo.x = d[mt][nf][0] + b0; lo.y = d[mt][nf][1] + b1;
                hi.x = d[mt][nf][2] + b0; hi.y = d[mt][nf][3] + b1;
                *reinterpret_cast<float2*>(&g_m[(size_t)prow * 64 + col]) = lo;
                *reinterpret_cast<float2*>(&g_m[(size_t)(prow + 8) * 64 + col]) = hi;
            }
        }
    }
}

// ================= mixing GEMM on tensor cores (tf32 mma.sync) =================
// C[p, n] = tanh( sum_k A[p,k] * w_mix[n,k] ),  A[p,k] = m[p,k>>2]*comb[p,k&3]
__global__ void __launch_bounds__(256, 2)
k_mix_mma() {
    __shared__ unsigned sA[128 * MMP];   // [m][k] tf32 bits
    __shared__ unsigned sB[128 * MMP];   // [n][k] tf32 bits

    const int t    = threadIdx.x;
    const int lane = t & 31;
    const int warp = t >> 5;
    const int gid  = lane >> 2;
    const int tig  = lane & 3;
    const int warpM = warp & 3;        // 0..3  -> 32 rows each
    const int warpN = warp >> 2;       // 0..1  -> 64 cols each
    const int p0 = blockIdx.x * 128;
    const int n0 = blockIdx.y * 128;

    const int srow = t >> 1;           // 0..127
    const int shalf = t & 1;

    const float4 cb = *reinterpret_cast<const float4*>(&g_comb[(size_t)(p0 + srow) * 4]);
    const float cbv[4] = {cb.x, cb.y, cb.z, cb.w};

    float d[2][8][4];
#pragma unroll
    for (int mt = 0; mt < 2; mt++)
#pragma unroll
        for (int nf = 0; nf < 8; nf++)
#pragma unroll
            for (int v = 0; v < 4; v++) d[mt][nf][v] = 0.f;

    float4 pmv;
    uint4  pwv[4];

    pmv = *reinterpret_cast<const float4*>(&g_m[(size_t)(p0 + srow) * 64 + shalf * 4]);
#pragma unroll
    for (int i = 0; i < 4; i++)
        pwv[i] = *reinterpret_cast<const uint4*>(
            &g_wD[(size_t)(n0 + srow) * 256 + shalf * 16 + i * 4]);

    for (int kc = 0; kc < 8; kc++) {
        __syncthreads();
        {
            const float mv[4] = {pmv.x, pmv.y, pmv.z, pmv.w};
            unsigned* ap = &sA[srow * MMP + shalf * 16];
#pragma unroll
            for (int i = 0; i < 4; i++)
#pragma unroll
                for (int j = 0; j < 4; j++)
                    ap[i * 4 + j] = f2tf32(mv[i] * cbv[j]);
            uint4* bp = reinterpret_cast<uint4*>(&sB[srow * MMP + shalf * 16]);
            bp[0] = pwv[0]; bp[1] = pwv[1]; bp[2] = pwv[2]; bp[3] = pwv[3];
        }
        __syncthreads();

        if (kc + 1 < 8) {
            int k0 = (kc + 1) * 32;
            pmv = *reinterpret_cast<const float4*>(
                &g_m[(size_t)(p0 + srow) * 64 + (k0 >> 2) + shalf * 4]);
#pragma unroll
            for (int i = 0; i < 4; i++)
                pwv[i] = *reinterpret_cast<const uint4*>(
                    &g_wD[(size_t)(n0 + srow) * 256 + k0 + shalf * 16 + i * 4]);
        }

#pragma unroll
        for (int ks = 0; ks < 4; ks++) {
            const int kb = ks * 8;
            unsigned a[2][4];
#pragma unroll
            for (int mt = 0; mt < 2; mt++) {
                const int mb = warpM * 32 + mt * 16;
                a[mt][0] = sA[(mb + gid) * MMP + kb + tig];
                a[mt][1] = sA[(mb + gid + 8) * MMP + kb + tig];
                a[mt][2] = sA[(mb + gid) * MMP + kb + tig + 4];
                a[mt][3] = sA[(mb + gid + 8) * MMP + kb + tig + 4];
            }
#pragma unroll
            for (int nf = 0; nf < 8; nf++) {
                unsigned b[2];
                const int nb = warpN * 64 + nf * 8 + gid;
                b[0] = sB[nb * MMP + kb + tig];
                b[1] = sB[nb * MMP + kb + tig + 4];
                mma_tf32(d[0][nf], a[0], b);
                mma_tf32(d[1][nf], a[1], b);
            }
        }
    }

#pragma unroll
    for (int mt = 0; mt < 2; mt++) {
        const int prow = p0 + warpM * 32 + mt * 16 + gid;
#pragma unroll
        for (int nf = 0; nf < 8; nf++) {
            const int col = n0 + warpN * 64 + nf * 8 + tig * 2;
            float2 lo, hi;
            lo.x = fast_tanh(d[mt][nf][0]); lo.y = fast_tanh(d[mt][nf][1]);
            hi.x = fast_tanh(d[mt][nf][2]); hi.y = fast_tanh(d[mt][nf][3]);
            *reinterpret_cast<float2*>(&g_coeffs[(size_t)prow * 256 + col]) = lo;
            *reinterpret_cast<float2*>(&g_coeffs[(size_t)(prow + 8) * 256 + col]) = hi;
        }
    }
}

// ================= atom-level GEMM (small M): 64x64 tiles =================
// MODE 4: norm @ w_post1^T, silu -> g_t1
// MODE 5: t1 @ w_post2^T, silu -> g_h2[:, 320:384]
// MODE 6: h2 @ w_node1^T, silu -> g_t2
// MODE 7: t2 @ w_node2^T, q + silu(.) -> out
template <int MODE>
__global__ void k_gemm(const float* __restrict__ W, const float* __restrict__ bias,
                       const float* __restrict__ x1, float* __restrict__ outp) {
    constexpr int M  = NATOMS;
    constexpr int KT = (MODE == 4) ? 16 : (MODE == 5) ? 4 : (MODE == 6) ? 24 : 4;
    constexpr int KW = (MODE == 4) ? 256 : (MODE == 5) ? 64 : (MODE == 6) ? 384 : 64;
    constexpr int LDA = (MODE == 4) ? 256 : (MODE == 6) ? 384 : 64;
    constexpr int LDC = (MODE == 5) ? 384 : 64;

    const float* A;
    float* C;
    if constexpr (MODE == 4)      { A = g_norm;   C = g_t1;      }
    else if constexpr (MODE == 5) { A = g_t1;     C = g_h2 + 320;}
    else if constexpr (MODE == 6) { A = g_h2;     C = g_t2;      }
    else                          { A = g_t2;     C = outp;      }

    __shared__ __align__(16) float sA[16 * 68];
    __shared__ __align__(16) float sW[16 * 68];

    int t  = threadIdx.x;
    int p0 = blockIdx.x * 64;
    int tx = t & 15, ty = t >> 4;
    int am   = t >> 2;
    int ak   = (t & 3) * 4;
    int arow = p0 + am;

    float acc[4][4];
#pragma unroll
    for (int i = 0; i < 4; i++)
#pragma unroll
        for (int j = 0; j < 4; j++) acc[i][j] = 0.f;

    for (int kt = 0; kt < KT; kt++) {
        int k0 = kt * 16;
        float4 av = make_float4(0.f, 0.f, 0.f, 0.f);
        if (arow < M)
            av = *reinterpret_cast<const float4*>(A + (size_t)arow * LDA + k0 + ak);
        float wv[4];
#pragma unroll
        for (int j = 0; j < 4; j++) {
            int k = k0 + ak + j;
            wv[j] = (k < KW) ? __ldg(&W[(size_t)am * KW + k]) : 0.f;
        }
        __syncthreads();
        sA[(ak + 0) * 68 + am] = av.x; sA[(ak + 1) * 68 + am] = av.y;
        sA[(ak + 2) * 68 + am] = av.z; sA[(ak + 3) * 68 + am] = av.w;
#pragma unroll
        for (int j = 0; j < 4; j++) sW[(ak + j) * 68 + am] = wv[j];
        __syncthreads();
#pragma unroll
        for (int kk = 0; kk < 16; kk++) {
            float4 a = *reinterpret_cast<const float4*>(&sA[kk * 68 + ty * 4]);
            float4 b = *reinterpret_cast<const float4*>(&sW[kk * 68 + tx * 4]);
            acc[0][0] += a.x * b.x; acc[0][1] += a.x * b.y; acc[0][2] += a.x * b.z; acc[0][3] += a.x * b.w;
            acc[1][0] += a.y * b.x; acc[1][1] += a.y * b.y; acc[1][2] += a.y * b.z; acc[1][3] += a.y * b.w;
            acc[2][0] += a.z * b.x; acc[2][1] += a.z * b.y; acc[2][2] += a.z * b.z; acc[2][3] += a.z * b.w;
            acc[3][0] += a.w * b.x; acc[3][1] += a.w * b.y; acc[3][2] += a.w * b.z; acc[3][3] += a.w * b.w;
        }
    }

#pragma unroll
    for (int i = 0; i < 4; i++) {
        int p = p0 + ty * 4 + i;
        if (p >= M) continue;
#pragma unroll
        for (int j = 0; j < 4; j++) {
            int gn = tx * 4 + j;
            float v = acc[i][j];
            if constexpr (MODE == 7) {
                C[(size_t)p * LDC + gn] = x1[(size_t)p * 64 + gn] + siluf(v + bias[gn]);
            } else {
                C[(size_t)p * LDC + gn] = siluf(v + bias[gn]);
            }
        }
    }
}

// ---------------- attention logits + segment max + degree counts ----------------
__global__ void k_att(const float* __restrict__ w_att, const float* __restrict__ b_att,
                      const int* __restrict__ idx_j) {
    int p    = blockIdx.x * 8 + (threadIdx.x >> 5);
    int lane = threadIdx.x & 31;
    const float* mr = g_m + (size_t)p * 64;
    float m1 = mr[lane], m2 = mr[32 + lane];
    float pa[4];
#pragma unroll
    for (int a = 0; a < 4; a++)
        pa[a] = __ldg(&w_att[a * 64 + lane]) * m1 + __ldg(&w_att[a * 64 + 32 + lane]) * m2;
#pragma unroll
    for (int o = 16; o > 0; o >>= 1)
#pragma unroll
        for (int a = 0; a < 4; a++) pa[a] += __shfl_xor_sync(0xffffffffu, pa[a], o);
    if (lane == 0) {
        int j = idx_j[p];
#pragma unroll
        for (int a = 0; a < 4; a++) {
            float v = pa[a] + b_att[a];
            v = (v >= 0.f) ? v : 2.f * expm1f(0.5f * v);   // celu alpha=2
            g_att[p * 4 + a] = v;
            atomicMaxFloat(&g_segmax[j * 4 + a], v);
        }
        atomicAdd(&g_counts[j], 1);
    }
}

// ---------------- softmax numerators + denominators ----------------
__global__ void k_exp(const int* __restrict__ idx_j) {
    int p = blockIdx.x * blockDim.x + threadIdx.x;
    if (p >= NPAIRS) return;
    int j = idx_j[p];
#pragma unroll
    for (int a = 0; a < 4; a++) {
        float v = __expf(g_att[p * 4 + a] - g_segmax[j * 4 + a]);
        g_e[p * 4 + a] = v;
        atomicAdd(&g_denom[j * 4 + a], v);
    }
}

// ---------------- comb = e / denom[idx_j] ----------------
__global__ void k_comb(const int* __restrict__ idx_j) {
    int p = blockIdx.x * blockDim.x + threadIdx.x;
    if (p >= NPAIRS) return;
    int j = idx_j[p];
    float4 e4 = *reinterpret_cast<const float4*>(&g_e[(size_t)p * 4]);
    float4 d4 = *reinterpret_cast<const float4*>(&g_denom[(size_t)j * 4]);
    float4 c4 = make_float4(e4.x / d4.x, e4.y / d4.y, e4.z / d4.z, e4.w / d4.w);
    *reinterpret_cast<float4*>(&g_comb[(size_t)p * 4]) = c4;
}

// ---------------- exclusive scan of counts -> offs (single block) ----------------
__global__ void k_scan() {
    __shared__ int part[1024];
    int tid = threadIdx.x;
    int base = tid * 10;
    int loc[10];
    int s = 0;
#pragma unroll
    for (int j = 0; j < 10; j++) {
        int idx = base + j;
        int v = (idx < NATOMS) ? g_counts[idx] : 0;
        loc[j] = s; s += v;
    }
    part[tid] = s;
    __syncthreads();
    for (int off = 1; off < 1024; off <<= 1) {
        int v = (tid >= off) ? part[tid - off] : 0;
        __syncthreads();
        part[tid] += v;
        __syncthreads();
    }
    int pre = (tid > 0) ? part[tid - 1] : 0;
#pragma unroll
    for (int j = 0; j < 10; j++) {
        int idx = base + j;
        if (idx < NATOMS) g_offs[idx] = pre + loc[j];
    }
    if (tid == 1023) g_offs[NATOMS] = part[1023];
}

// ---------------- fill CSR edge order ----------------
__global__ void k_fill(const int* __restrict__ idx_j) {
    int p = blockIdx.x * blockDim.x + threadIdx.x;
    if (p >= NPAIRS) return;
    int j = idx_j[p];
    int pos = atomicAdd(&g_cursor[j], 1);
    g_order[g_offs[j] + pos] = p;
}

// ---------------- per-atom gather reductions (single pass, acc in regs) ----------
__global__ void k_segreduce(const float* __restrict__ q, const float* __restrict__ r_ij,
                            const float* __restrict__ d_ij) {
    int n    = blockIdx.x * 8 + (threadIdx.x >> 5);
    int lane = threadIdx.x & 31;
    if (n >= NATOMS) return;
    int beg = g_offs[n], end = g_offs[n + 1];
    int cnt = end - beg;
    float inv = 1.f / (float)max(cnt, 1);
    g_h2[(size_t)n * 384 + lane]      = q[(size_t)n * 64 + lane];
    g_h2[(size_t)n * 384 + 32 + lane] = q[(size_t)n * 64 + 32 + lane];

    const int hh   = lane & 3;
    const int fsub = lane >> 2;
    float ax[8], ay[8], az[8], aq[8];
#pragma unroll
    for (int cr = 0; cr < 8; cr++) { ax[cr] = ay[cr] = az[cr] = aq[cr] = 0.f; }

    for (int tt = beg; tt < end; tt++) {
        int p = g_order[tt];
        float dv   = __ldg(&d_ij[p]);
        float rinv = 1.f / (dv + 1e-5f);
        float rx = __ldg(&r_ij[p * 3 + 0]) * rinv;
        float ry = __ldg(&r_ij[p * 3 + 1]) * rinv;
        float rz = __ldg(&r_ij[p * 3 + 2]) * rinv;
        float4 cb4 = __ldg(reinterpret_cast<const float4*>(&g_comb[(size_t)p * 4]));
        float cw = (hh == 0) ? cb4.x : (hh == 1) ? cb4.y : (hh == 2) ? cb4.z : cb4.w;
        float m1 = __ldg(&g_m[(size_t)p * 64 + lane]);
        float m2 = __ldg(&g_m[(size_t)p * 64 + 32 + lane]);
        const float* crow = &g_coeffs[(size_t)p * 256];
#pragma unroll
        for (int cr = 0; cr < 8; cr++) {
            float co = __ldg(&crow[cr * 32 + lane]);
            float mv = (cr < 4) ? __shfl_sync(0xffffffffu, m1, cr * 8 + fsub)
                                : __shfl_sync(0xffffffffu, m2, (cr - 4) * 8 + fsub);
            aq[cr] += mv * cw;
            ax[cr] += co * rx;
            ay[cr] += co * ry;
            az[cr] += co * rz;
        }
    }

#pragma unroll
    for (int cr = 0; cr < 8; cr++) {
        int c = cr * 32 + lane;
        float mx = ax[cr] * inv, my = ay[cr] * inv, mz = az[cr] * inv;
        g_norm[(size_t)n * 256 + c]    = mx * mx + my * my + mz * mz;
        g_h2[(size_t)n * 384 + 64 + c] = aq[cr];
    }
}

// ---------------- launch ----------------
extern "C" void kernel_launch(void* const* d_in, const int* in_sizes, int n_in,
                              void* d_out, int out_size) {
    (void)in_sizes; (void)n_in; (void)out_size;
    const float* q       = (const float*)d_in[0];
    const float* r_ij    = (const float*)d_in[2];
    const float* d_ij    = (const float*)d_in[3];
    const int*   idx_i   = (const int*)d_in[4];
    const int*   idx_j   = (const int*)d_in[5];
    const float* rbf_off = (const float*)d_in[6];
    const float* rbf_w   = (const float*)d_in[7];
    const float* w_in    = (const float*)d_in[8];
    const float* b_in    = (const float*)d_in[9];
    const float* w_out1  = (const float*)d_in[10];
    const float* b_out1  = (const float*)d_in[11];
    const float* w_out2  = (const float*)d_in[12];
    const float* b_out2  = (const float*)d_in[13];
    const float* w_att   = (const float*)d_in[14];
    const float* b_att   = (const float*)d_in[15];
    const float* w_mix   = (const float*)d_in[16];
    const float* w_post1 = (const float*)d_in[17];
    const float* b_post1 = (const float*)d_in[18];
    const float* w_post2 = (const float*)d_in[19];
    const float* b_post2 = (const float*)d_in[20];
    const float* w_node1 = (const float*)d_in[21];
    const float* b_node1 = (const float*)d_in[22];
    const float* w_node2 = (const float*)d_in[23];
    const float* b_node2 = (const float*)d_in[24];
    float* out = (float*)d_out;

    unsigned* dwA; unsigned* dwB; unsigned* dwC; unsigned* dwD;
    cudaGetSymbolAddress((void**)&dwA, g_wA);
    cudaGetSymbolAddress((void**)&dwB, g_wB);
    cudaGetSymbolAddress((void**)&dwC, g_wC);
    cudaGetSymbolAddress((void**)&dwD, g_wD);

    k_init<<<157, 256>>>();
    k_cvtw<<<32, 256>>>(w_in,   dwA, 50, 128, 128, 64 * 128);
    k_cvtw<<<48, 256>>>(w_out1, dwB, 64, 179, 192, 64 * 192);
    k_cvtw<<<16, 256>>>(w_out2, dwC, 64, 64, 64, 64 * 64);
    k_cvtw<<<256, 256>>>(w_mix, dwD, 256, 256, 256, 256 * 256);
    k_gather<<<NPAIRS / 8, 256>>>(q, idx_i, idx_j, d_ij);
    k_edge_mma<0><<<NPAIRS / 128, 256>>>(b_in, d_ij, rbf_off, rbf_w);
    k_edge_mma<1><<<NPAIRS / 128, 256>>>(b_out1, nullptr, nullptr, nullptr);
    k_edge_mma<2><<<NPAIRS / 128, 256>>>(b_out2, nullptr, nullptr, nullptr);
    k_att<<<NPAIRS / 8, 256>>>(w_att, b_att, idx_j);
    k_exp<<<(NPAIRS + 255) / 256, 256>>>(idx_j);
    k_comb<<<(NPAIRS + 255) / 256, 256>>>(idx_j);
    k_scan<<<1, 1024>>>();
    k_fill<<<(NPAIRS + 255) / 256, 256>>>(idx_j);
    k_mix_mma<<<dim3(NPAIRS / 128, 2), 256>>>();
    k_segreduce<<<NATOMS / 8, 256>>>(q, r_ij, d_ij);
    k_gemm<4><<<157, 256>>>(w_post1, b_post1, nullptr, nullptr);
    k_gemm<5><<<157, 256>>>(w_post2, b_post2, nullptr, nullptr);
    k_gemm<6><<<157, 256>>>(w_node1, b_node1, nullptr, nullptr);
    k_gemm<7><<<157, 256>>>(w_node2, b_node2, q, out);
}